// round 4
// baseline (speedup 1.0000x reference)
#include <cuda_runtime.h>

// Problem constants (fixed by the reference)
#define Bn 32
#define Nn 1024
#define Fn 128
#define Dn 128
#define SL 16                       // slice blocks per batch
#define RPB 64                      // rows per slice block
#define NBLK (Bn * SL)              // 512 blocks

// Scratch (static __device__ — no allocation allowed)
__device__ float g_XsumP[Bn][SL][Fn];
__device__ float g_u[Bn][Fn];
__device__ float g_c[Bn];
__device__ float g_agg[Bn][Nn];
__device__ float g_M[Bn][SL];
__device__ float g_S[Bn][SL];
__device__ float g_acc[Bn][SL][Fn];
// Monotonic sync state — never reset; works across graph replays because
// last-arrival is detected by (old % 16 == 15) and the flag is compared
// against its value read at block entry.
__device__ unsigned g_cntA[Bn];
__device__ unsigned g_cntC[Bn];
__device__ volatile unsigned g_uflag[Bn];

__global__ __launch_bounds__(256, 4)
void ga_fused(const float* __restrict__ X, const float* __restrict__ mask,
              const float* __restrict__ Wq, const float* __restrict__ bq,
              const float* __restrict__ Wk, const float* __restrict__ bk,
              const float* __restrict__ Wv, const float* __restrict__ bv,
              float* __restrict__ attn, float* __restrict__ ctx) {
    int bid = blockIdx.x, t = threadIdx.x;
    int b = bid >> 4, s = bid & 15;
    int w = t >> 5, lane = t & 31;

    __shared__ float4 shV[8][32];        // A: col-sum partials; C: acc partials
    __shared__ float shU[Fn];            // u[b]
    __shared__ float shT0[Fn], shT1[Fn]; // B: Xs/Ks ; D: Y + M/S
    __shared__ float shRed[128];
    __shared__ float shC;
    __shared__ int   shLast;
    __shared__ float shMw[8], shSw[8];

    unsigned uf0 = g_uflag[b];           // entry value (stable: pre-increment)

    // ---------------- Phase A: load X rows into regs, column-sum ------------
    int row0 = s * RPB + w * 8;
    const float4* Xr = (const float4*)(X + ((size_t)b * Nn + row0) * Fn);
    float4 x[8];
    #pragma unroll
    for (int r = 0; r < 8; r++) x[r] = Xr[(size_t)r * 32 + lane];
    float mv = (lane < 8) ? mask[b * Nn + row0 + lane] : 0.f;

    {
        float4 cs = x[0];
        #pragma unroll
        for (int r = 1; r < 8; r++) {
            cs.x += x[r].x; cs.y += x[r].y; cs.z += x[r].z; cs.w += x[r].w;
        }
        shV[w][lane] = cs;
    }
    __syncthreads();
    if (t < 32) {
        float4 sum = shV[0][t];
        #pragma unroll
        for (int g = 1; g < 8; g++) {
            float4 p = shV[g][t];
            sum.x += p.x; sum.y += p.y; sum.z += p.z; sum.w += p.w;
        }
        ((float4*)g_XsumP[b][s])[t] = sum;
    }
    __threadfence();
    if (t == 0) {
        unsigned old = atomicAdd(&g_cntA[b], 1u);
        shLast = ((old & 15u) == 15u);
    }
    __syncthreads();
    bool lastA = (shLast != 0);

    // ---------------- Phase B: last arrival computes u, c -------------------
    if (lastA) {
        __threadfence();
        if (t < 128) {
            float sm = 0.f;
            #pragma unroll
            for (int j = 0; j < SL; j++) sm += g_XsumP[b][j][t];
            shT0[t] = sm;                          // Xsum
        }
        __syncthreads();
        if (t < 128) {
            float acc = (float)Nn * bk[t];
            #pragma unroll 8
            for (int f = 0; f < Fn; f++) acc += shT0[f] * Wk[f * Dn + t];
            shT1[t] = acc;                         // ksum
        }
        __syncthreads();
        if (t < 128) {
            float ua = 0.f;
            #pragma unroll 8
            for (int d = 0; d < Dn; d++) ua += Wq[t * Dn + d] * shT1[d];
            g_u[b][t] = ua;
            shU[t] = ua;
            shRed[t] = bq[t] * shT1[t];
        }
        __syncthreads();
        for (int off = 64; off > 0; off >>= 1) {
            if (t < off) shRed[t] += shRed[t + off];
            __syncthreads();
        }
        if (t == 0) {
            g_c[b] = shRed[0];
            shC = shRed[0];
            __threadfence();
            g_uflag[b] = uf0 + 1u;                 // release
        }
        __syncthreads();
    } else {
        if (t == 0) { while (g_uflag[b] == uf0) { } }
        __syncthreads();
        __threadfence();
        if (t < 128) shU[t] = g_u[b][t];
        if (t == 0) shC = g_c[b];
        __syncthreads();
    }

    // ---------------- Phase C: agg + online-softmax acc (x still in regs) ---
    float c = shC;
    float4 uv = ((float4*)shU)[lane];
    float M = -3.0e38f, Ssum = 0.f;
    float4 acc = make_float4(0.f, 0.f, 0.f, 0.f);
    #pragma unroll
    for (int r = 0; r < 8; r++) {
        float d = x[r].x * uv.x + x[r].y * uv.y + x[r].z * uv.z + x[r].w * uv.w;
        #pragma unroll
        for (int off = 16; off > 0; off >>= 1)
            d += __shfl_xor_sync(0xffffffffu, d, off);
        float mval = __shfl_sync(0xffffffffu, mv, r);
        float a = (mval != 0.f) ? 0.08838834764831843f * (d + c) : -1e9f;
        if (lane == 0) g_agg[b][row0 + r] = a;
        float newM = fmaxf(M, a);
        float sc = __expf(M - newM);
        float ev = __expf(a - newM);
        Ssum = Ssum * sc + ev;
        acc.x = acc.x * sc + ev * x[r].x;
        acc.y = acc.y * sc + ev * x[r].y;
        acc.z = acc.z * sc + ev * x[r].z;
        acc.w = acc.w * sc + ev * x[r].w;
        M = newM;
    }
    if (lane == 0) { shMw[w] = M; shSw[w] = Ssum; }
    __syncthreads();                 // shV reuse safe (phase A done)
    shV[w][lane] = acc;
    __syncthreads();
    if (t < 32) {
        float bM = shMw[0];
        #pragma unroll
        for (int j = 1; j < 8; j++) bM = fmaxf(bM, shMw[j]);
        float Sb = 0.f;
        float4 ya = make_float4(0.f, 0.f, 0.f, 0.f);
        #pragma unroll
        for (int j = 0; j < 8; j++) {
            float f = __expf(shMw[j] - bM);
            Sb += f * shSw[j];
            float4 p = shV[j][t];
            ya.x += f * p.x; ya.y += f * p.y; ya.z += f * p.z; ya.w += f * p.w;
        }
        ((float4*)g_acc[b][s])[t] = ya;
        if (t == 0) { g_M[b][s] = bM; g_S[b][s] = Sb; }
    }
    __threadfence();
    if (t == 0) {
        unsigned old = atomicAdd(&g_cntC[b], 1u);
        shLast = ((old & 15u) == 15u);
    }
    __syncthreads();

    // ---------------- Phase D: last finisher merges + outputs ---------------
    if (shLast) {
        __threadfence();
        if (t < SL) { shMw[t & 7] = 0.f; }  // (no-op; keep structure simple)
        if (t < SL) { shT1[t] = g_M[b][t]; shT1[SL + t] = g_S[b][t]; }
        __syncthreads();
        float bM = -3.0e38f;
        #pragma unroll
        for (int j = 0; j < SL; j++) bM = fmaxf(bM, shT1[j]);
        float Z = 0.f;
        #pragma unroll
        for (int j = 0; j < SL; j++) Z += __expf(shT1[j] - bM) * shT1[SL + j];
        float invZ = 1.0f / Z;

        if (t < 128) {
            float y = 0.f;
            #pragma unroll
            for (int j = 0; j < SL; j++)
                y += __expf(shT1[j] - bM) * g_acc[b][j][t];
            shT0[t] = y * invZ;
        }
        // attn: 4 rows/thread, independent of shT0
        #pragma unroll
        for (int i = 0; i < 4; i++) {
            int n = t + i * 256;
            attn[b * Nn + n] = __expf(g_agg[b][n] - bM) * invZ;
        }
        __syncthreads();
        if (t < 128) {
            float a0 = 0.f, a1 = 0.f, a2 = 0.f, a3 = 0.f;
            #pragma unroll 8
            for (int f = 0; f < Fn; f += 4) {
                a0 += shT0[f]     * Wv[(f)     * Dn + t];
                a1 += shT0[f + 1] * Wv[(f + 1) * Dn + t];
                a2 += shT0[f + 2] * Wv[(f + 2) * Dn + t];
                a3 += shT0[f + 3] * Wv[(f + 3) * Dn + t];
            }
            ctx[b * Dn + t] = bv[t] + ((a0 + a1) + (a2 + a3));
        }
    }
}

extern "C" void kernel_launch(void* const* d_in, const int* in_sizes, int n_in,
                              void* d_out, int out_size) {
    const float* X    = (const float*)d_in[0];
    const float* mask = (const float*)d_in[1];
    const float* Wq   = (const float*)d_in[2];
    const float* bq   = (const float*)d_in[3];
    const float* Wk   = (const float*)d_in[4];
    const float* bk   = (const float*)d_in[5];
    const float* Wv   = (const float*)d_in[6];
    const float* bv   = (const float*)d_in[7];
    float* out  = (float*)d_out;
    float* attn = out;              // [B,N,1]
    float* ctx  = out + Bn * Nn;    // [B,D]

    ga_fused<<<NBLK, 256>>>(X, mask, Wq, bq, Wk, bk, Wv, bv, attn, ctx);
}

// round 5
// speedup vs baseline: 1.2187x; 1.2187x over previous
#include <cuda_runtime.h>

// Problem constants (fixed by the reference)
#define Bn 32
#define Nn 1024
#define Fn 128
#define Dn 128
#define SL 16                       // slice blocks per batch
#define RPB 64                      // rows per slice block
#define NBLK (Bn * SL)              // 512 blocks

// Scratch (static __device__ — no allocation allowed)
__device__ float g_XsumP[Bn][SL][Fn];
__device__ float g_u[Bn][Fn];
__device__ float g_c[Bn];
__device__ float g_agg[Bn][Nn];
__device__ float g_M[Bn][SL];
__device__ float g_S[Bn][SL];
__device__ float g_acc[Bn][SL][Fn];
// Monotonic counters (never reset; 16 increments per batch per launch,
// last arrival detected by (old & 15) == 15).
__device__ unsigned g_cntA[Bn];
__device__ unsigned g_cntC[Bn];

// ---------------------------------------------------------------------------
// KA: column-sum partials of X; last-arriving block per batch computes u, c.
__global__ __launch_bounds__(256, 4)
void kA(const float* __restrict__ X,
        const float* __restrict__ Wq, const float* __restrict__ bq,
        const float* __restrict__ Wk, const float* __restrict__ bk) {
    int bid = blockIdx.x, t = threadIdx.x;
    int b = bid >> 4, s = bid & 15;
    int w = t >> 5, lane = t & 31;

    __shared__ float4 shP[8][32];
    __shared__ int shLast;

    {
        const float4* Xr = (const float4*)(X + ((size_t)b * Nn + s * RPB + w * 8) * Fn);
        float4 cs = Xr[lane];
        #pragma unroll
        for (int r = 1; r < 8; r++) {
            float4 xx = Xr[(size_t)r * 32 + lane];
            cs.x += xx.x; cs.y += xx.y; cs.z += xx.z; cs.w += xx.w;
        }
        shP[w][lane] = cs;
    }
    __syncthreads();
    if (t < 32) {
        float4 sum = shP[0][t];
        #pragma unroll
        for (int g = 1; g < 8; g++) {
            float4 p = shP[g][t];
            sum.x += p.x; sum.y += p.y; sum.z += p.z; sum.w += p.w;
        }
        ((float4*)g_XsumP[b][s])[t] = sum;
    }
    __threadfence();
    if (t == 0) shLast = ((atomicAdd(&g_cntA[b], 1u) & 15u) == 15u);
    __syncthreads();
    if (!shLast) return;
    __threadfence();                 // acquire: all 16 partials visible

    // ---- tail: u = Wq @ ksum, c = bq . ksum (256 threads, split-K GEMVs) ---
    __shared__ float Xs[Fn], Ks[Fn], part[2][Fn], red[128];
    if (t < 128) {
        float sm = 0.f;
        #pragma unroll
        for (int j = 0; j < SL; j++) sm += g_XsumP[b][j][t];
        Xs[t] = sm;
    }
    __syncthreads();
    {
        int d = t & 127, h = t >> 7;          // h in {0,1}: half of the K range
        float acc = 0.f;
        #pragma unroll 8
        for (int f = h * 64; f < h * 64 + 64; f++) acc += Xs[f] * Wk[f * Dn + d];
        part[h][d] = acc;
    }
    __syncthreads();
    if (t < 128) Ks[t] = part[0][t] + part[1][t] + (float)Nn * bk[t];
    __syncthreads();
    {
        int d = t & 127, h = t >> 7;
        float acc = 0.f;
        #pragma unroll 8
        for (int f = h * 64; f < h * 64 + 64; f++) acc += Wq[d * Dn + f] * Ks[f];
        part[h][d] = acc;
    }
    __syncthreads();
    if (t < 128) {
        g_u[b][t] = part[0][t] + part[1][t];
        red[t] = bq[t] * Ks[t];
    }
    __syncthreads();
    for (int off = 64; off > 0; off >>= 1) {
        if (t < off) red[t] += red[t + off];
        __syncthreads();
    }
    if (t == 0) g_c[b] = red[0];
}

// ---------------------------------------------------------------------------
// KB: fused agg + online-softmax acc; last-arriving block per batch merges
//     the 16 partials and writes attn + context.
__global__ __launch_bounds__(256, 4)
void kB(const float* __restrict__ X, const float* __restrict__ mask,
        const float* __restrict__ Wv, const float* __restrict__ bv,
        float* __restrict__ attn, float* __restrict__ ctx) {
    int bid = blockIdx.x, t = threadIdx.x;
    int b = bid >> 4, s = bid & 15;
    int w = t >> 5, lane = t & 31;

    __shared__ float shU[Fn];
    __shared__ float shMw[8], shSw[8];
    __shared__ float4 shP[8][32];
    __shared__ int shLast;

    if (t < 128) shU[t] = g_u[b][t];
    __syncthreads();
    float c = g_c[b];
    float4 uv = ((float4*)shU)[lane];

    int row0 = s * RPB + w * 8;
    const float4* Xr = (const float4*)(X + ((size_t)b * Nn + row0) * Fn);
    float mv = (lane < 8) ? mask[b * Nn + row0 + lane] : 0.f;

    float M = -3.0e38f, Ssum = 0.f;
    float4 acc = make_float4(0.f, 0.f, 0.f, 0.f);
    #pragma unroll
    for (int r = 0; r < 8; r++) {
        float4 xr = Xr[(size_t)r * 32 + lane];
        float d = xr.x * uv.x + xr.y * uv.y + xr.z * uv.z + xr.w * uv.w;
        #pragma unroll
        for (int off = 16; off > 0; off >>= 1)
            d += __shfl_xor_sync(0xffffffffu, d, off);
        float mval = __shfl_sync(0xffffffffu, mv, r);
        float a = (mval != 0.f) ? 0.08838834764831843f * (d + c) : -1e9f;
        if (lane == 0) g_agg[b][row0 + r] = a;
        float newM = fmaxf(M, a);
        float sc = __expf(M - newM);
        float ev = __expf(a - newM);
        Ssum = Ssum * sc + ev;
        acc.x = acc.x * sc + ev * xr.x;
        acc.y = acc.y * sc + ev * xr.y;
        acc.z = acc.z * sc + ev * xr.z;
        acc.w = acc.w * sc + ev * xr.w;
        M = newM;
    }
    if (lane == 0) { shMw[w] = M; shSw[w] = Ssum; }
    shP[w][lane] = acc;
    __syncthreads();
    if (t < 32) {
        float bM = shMw[0];
        #pragma unroll
        for (int j = 1; j < 8; j++) bM = fmaxf(bM, shMw[j]);
        float Sb = 0.f;
        float4 ya = make_float4(0.f, 0.f, 0.f, 0.f);
        #pragma unroll
        for (int j = 0; j < 8; j++) {
            float f = __expf(shMw[j] - bM);
            Sb += f * shSw[j];
            float4 p = shP[j][t];
            ya.x += f * p.x; ya.y += f * p.y; ya.z += f * p.z; ya.w += f * p.w;
        }
        ((float4*)g_acc[b][s])[t] = ya;
        if (t == 0) { g_M[b][s] = bM; g_S[b][s] = Sb; }
    }
    __threadfence();
    if (t == 0) shLast = ((atomicAdd(&g_cntC[b], 1u) & 15u) == 15u);
    __syncthreads();
    if (!shLast) return;
    __threadfence();                 // acquire: all 16 partials visible

    // ---- tail: merge 16 (M, S, acc) partials; write attn + context ---------
    __shared__ float shM[SL], shS[SL], shY[Fn], part[2][Fn];
    if (t < SL) { shM[t] = g_M[b][t]; shS[t] = g_S[b][t]; }
    __syncthreads();
    float bM = -3.0e38f;
    #pragma unroll
    for (int j = 0; j < SL; j++) bM = fmaxf(bM, shM[j]);
    float Z = 0.f;
    #pragma unroll
    for (int j = 0; j < SL; j++) Z += __expf(shM[j] - bM) * shS[j];
    float invZ = 1.0f / Z;

    if (t < 128) {
        float y = 0.f;
        #pragma unroll
        for (int j = 0; j < SL; j++)
            y += __expf(shM[j] - bM) * g_acc[b][j][t];
        shY[t] = y * invZ;
    }
    // attn: 4 values per thread (independent of shY)
    #pragma unroll
    for (int i = 0; i < 4; i++) {
        int n = t + i * 256;
        attn[b * Nn + n] = __expf(g_agg[b][n] - bM) * invZ;
    }
    __syncthreads();
    // context GEMV split across 256 threads (2 per output)
    {
        int d = t & 127, h = t >> 7;
        float a = 0.f;
        #pragma unroll 8
        for (int f = h * 64; f < h * 64 + 64; f++) a += shY[f] * Wv[f * Dn + d];
        part[h][d] = a;
    }
    __syncthreads();
    if (t < 128)
        ctx[b * Dn + t] = bv[t] + part[0][t] + part[1][t];
}

// ---------------------------------------------------------------------------
extern "C" void kernel_launch(void* const* d_in, const int* in_sizes, int n_in,
                              void* d_out, int out_size) {
    const float* X    = (const float*)d_in[0];
    const float* mask = (const float*)d_in[1];
    const float* Wq   = (const float*)d_in[2];
    const float* bq   = (const float*)d_in[3];
    const float* Wk   = (const float*)d_in[4];
    const float* bk   = (const float*)d_in[5];
    const float* Wv   = (const float*)d_in[6];
    const float* bv   = (const float*)d_in[7];
    float* out  = (float*)d_out;
    float* attn = out;              // [B,N,1]
    float* ctx  = out + Bn * Nn;    // [B,D]

    kA<<<NBLK, 256>>>(X, Wq, bq, Wk, bk);
    kB<<<NBLK, 256>>>(X, mask, Wv, bv, attn, ctx);
}

// round 6
// speedup vs baseline: 2.0762x; 1.7036x over previous
#include <cuda_runtime.h>

// Problem constants (fixed by the reference)
#define Bn 32
#define Nn 1024
#define Fn 128
#define Dn 128
#define SL 16                       // slice blocks per batch
#define RPB 64                      // rows per slice block
#define SCALE 0.08838834764831843f  // 128^-0.5

// Scratch (static __device__ — no allocation allowed)
__device__ float g_XsumP[Bn][SL][Fn];
__device__ float g_u[Bn][Fn];
__device__ float g_c[Bn];
__device__ float g_agg[Bn][Nn];
__device__ float g_M[Bn][SL];
__device__ float g_S[Bn][SL];
__device__ float g_acc[Bn][SL][Fn];

// ---------------------------------------------------------------------------
// K1: column-sum partials of X. grid (B, SL) x 256.
__global__ __launch_bounds__(256, 4)
void k1(const float* __restrict__ X) {
    int b = blockIdx.x, s = blockIdx.y, t = threadIdx.x;
    int w = t >> 5, lane = t & 31;
    __shared__ float4 shP[8][32];
    const float4* Xr = (const float4*)(X + ((size_t)b * Nn + s * RPB + w * 8) * Fn);
    float4 cs = Xr[lane];
    #pragma unroll
    for (int r = 1; r < 8; r++) {
        float4 xx = Xr[(size_t)r * 32 + lane];
        cs.x += xx.x; cs.y += xx.y; cs.z += xx.z; cs.w += xx.w;
    }
    shP[w][lane] = cs;
    __syncthreads();
    if (t < 32) {
        float4 sum = shP[0][t];
        #pragma unroll
        for (int g = 1; g < 8; g++) {
            float4 p = shP[g][t];
            sum.x += p.x; sum.y += p.y; sum.z += p.z; sum.w += p.w;
        }
        ((float4*)g_XsumP[b][s])[t] = sum;
    }
}

// ---------------------------------------------------------------------------
// K2: ksum -> u, c. grid B x 256 (split-K GEMVs, 2 threads per output).
__global__ __launch_bounds__(256, 4)
void k2(const float* __restrict__ Wq, const float* __restrict__ bq,
        const float* __restrict__ Wk, const float* __restrict__ bk) {
    int b = blockIdx.x, t = threadIdx.x;
    __shared__ float Xs[Fn], Ks[Fn], part[2][Fn], red[128];
    if (t < 128) {
        float sm = 0.f;
        #pragma unroll
        for (int j = 0; j < SL; j++) sm += g_XsumP[b][j][t];
        Xs[t] = sm;
    }
    __syncthreads();
    {
        int d = t & 127, h = t >> 7;
        float acc = 0.f;
        #pragma unroll 8
        for (int f = h * 64; f < h * 64 + 64; f++) acc += Xs[f] * Wk[f * Dn + d];
        part[h][d] = acc;
    }
    __syncthreads();
    if (t < 128) Ks[t] = part[0][t] + part[1][t] + (float)Nn * bk[t];
    __syncthreads();
    {
        int d = t & 127, h = t >> 7;
        float acc = 0.f;
        #pragma unroll 8
        for (int f = h * 64; f < h * 64 + 64; f++) acc += Wq[d * Dn + f] * Ks[f];
        part[h][d] = acc;
    }
    __syncthreads();
    if (t < 128) {
        g_u[b][t] = part[0][t] + part[1][t];
        red[t] = bq[t] * Ks[t];
    }
    __syncthreads();
    for (int off = 64; off > 0; off >>= 1) {
        if (t < off) red[t] += red[t + off];
        __syncthreads();
    }
    if (t == 0) g_c[b] = red[0];
}

// ---------------------------------------------------------------------------
// K3: fused agg + softmax partials. grid (B, SL) x 256, 8 rows/warp.
// All 8 row-dots reduced with interleaved (pipelined) butterflies; local
// 8-way max replaces the serial online-softmax carry.
__global__ __launch_bounds__(256, 4)
void k3(const float* __restrict__ X, const float* __restrict__ mask) {
    int b = blockIdx.x, s = blockIdx.y, t = threadIdx.x;
    int w = t >> 5, lane = t & 31;
    __shared__ float shU[Fn];
    __shared__ float shMw[8], shSw[8];
    __shared__ float4 shP[8][32];

    if (t < 128) shU[t] = g_u[b][t];
    __syncthreads();
    float c = g_c[b];
    float4 uv = ((float4*)shU)[lane];

    int row0 = s * RPB + w * 8;
    const float4* Xr = (const float4*)(X + ((size_t)b * Nn + row0) * Fn);
    float4 x[8];
    float d[8];
    #pragma unroll
    for (int r = 0; r < 8; r++) {
        x[r] = Xr[(size_t)r * 32 + lane];
        d[r] = x[r].x * uv.x + x[r].y * uv.y + x[r].z * uv.z + x[r].w * uv.w;
    }
    // interleaved butterflies: 8 independent reductions pipeline their latency
    #pragma unroll
    for (int off = 16; off > 0; off >>= 1) {
        #pragma unroll
        for (int r = 0; r < 8; r++)
            d[r] += __shfl_xor_sync(0xffffffffu, d[r], off);
    }
    const float* mrow = mask + b * Nn + row0;
    float a[8];
    #pragma unroll
    for (int r = 0; r < 8; r++)
        a[r] = (__ldg(mrow + r) != 0.f) ? SCALE * (d[r] + c) : -1e9f;

    // store agg: lane r holds a[r] via predicated selects
    {
        float myA = a[0];
        #pragma unroll
        for (int r = 1; r < 8; r++) if (lane == r) myA = a[r];
        if (lane < 8) g_agg[b][row0 + lane] = myA;
    }

    float M8 = a[0];
    #pragma unroll
    for (int r = 1; r < 8; r++) M8 = fmaxf(M8, a[r]);
    float ev[8];
    float Ssum = 0.f;
    float4 acc = make_float4(0.f, 0.f, 0.f, 0.f);
    #pragma unroll
    for (int r = 0; r < 8; r++) {
        ev[r] = __expf(a[r] - M8);
        Ssum += ev[r];
    }
    #pragma unroll
    for (int r = 0; r < 8; r++) {
        acc.x += ev[r] * x[r].x;
        acc.y += ev[r] * x[r].y;
        acc.z += ev[r] * x[r].z;
        acc.w += ev[r] * x[r].w;
    }

    if (lane == 0) { shMw[w] = M8; shSw[w] = Ssum; }
    shP[w][lane] = acc;
    __syncthreads();
    if (t < 32) {
        float bM = shMw[0];
        #pragma unroll
        for (int j = 1; j < 8; j++) bM = fmaxf(bM, shMw[j]);
        float Sb = 0.f;
        float4 ya = make_float4(0.f, 0.f, 0.f, 0.f);
        #pragma unroll
        for (int j = 0; j < 8; j++) {
            float f = __expf(shMw[j] - bM);
            Sb += f * shSw[j];
            float4 p = shP[j][t];
            ya.x += f * p.x; ya.y += f * p.y; ya.z += f * p.z; ya.w += f * p.w;
        }
        ((float4*)g_acc[b][s])[t] = ya;
        if (t == 0) { g_M[b][s] = bM; g_S[b][s] = Sb; }
    }
}

// ---------------------------------------------------------------------------
// K4: finalize. grid (B, 4) x 256. Every block: 256 attn rows.
// Block i==0 additionally merges acc partials and writes context.
__global__ __launch_bounds__(256, 4)
void k4(const float* __restrict__ Wv, const float* __restrict__ bv,
        float* __restrict__ attn, float* __restrict__ ctx) {
    int b = blockIdx.x, i = blockIdx.y, t = threadIdx.x;
    __shared__ float shM[SL], shS[SL];
    __shared__ float shB[2];
    if (t < SL) { shM[t] = g_M[b][t]; shS[t] = g_S[b][t]; }
    __syncthreads();
    if (t == 0) {
        float bM = shM[0];
        #pragma unroll
        for (int j = 1; j < SL; j++) bM = fmaxf(bM, shM[j]);
        float Z = 0.f;
        #pragma unroll
        for (int j = 0; j < SL; j++) Z += __expf(shM[j] - bM) * shS[j];
        shB[0] = bM; shB[1] = 1.0f / Z;
    }
    __syncthreads();
    float bM = shB[0], invZ = shB[1];

    int n = i * 256 + t;
    attn[b * Nn + n] = __expf(g_agg[b][n] - bM) * invZ;

    if (i == 0) {
        __shared__ float shY[Fn], part[2][Fn];
        if (t < 128) {
            float y = 0.f;
            #pragma unroll
            for (int j = 0; j < SL; j++)
                y += __expf(shM[j] - bM) * g_acc[b][j][t];
            shY[t] = y * invZ;
        }
        __syncthreads();
        {
            int d = t & 127, h = t >> 7;
            float a = 0.f;
            #pragma unroll 8
            for (int f = h * 64; f < h * 64 + 64; f++) a += shY[f] * Wv[f * Dn + d];
            part[h][d] = a;
        }
        __syncthreads();
        if (t < 128)
            ctx[b * Dn + t] = bv[t] + part[0][t] + part[1][t];
    }
}

// ---------------------------------------------------------------------------
extern "C" void kernel_launch(void* const* d_in, const int* in_sizes, int n_in,
                              void* d_out, int out_size) {
    const float* X    = (const float*)d_in[0];
    const float* mask = (const float*)d_in[1];
    const float* Wq   = (const float*)d_in[2];
    const float* bq   = (const float*)d_in[3];
    const float* Wk   = (const float*)d_in[4];
    const float* bk   = (const float*)d_in[5];
    const float* Wv   = (const float*)d_in[6];
    const float* bv   = (const float*)d_in[7];
    float* out  = (float*)d_out;
    float* attn = out;              // [B,N,1]
    float* ctx  = out + Bn * Nn;    // [B,D]

    k1<<<dim3(Bn, SL), 256>>>(X);
    k2<<<Bn, 256>>>(Wq, bq, Wk, bk);
    k3<<<dim3(Bn, SL), 256>>>(X, mask);
    k4<<<dim3(Bn, 4), 256>>>(Wv, bv, attn, ctx);
}